// round 6
// baseline (speedup 1.0000x reference)
#include <cuda_runtime.h>
#include <cstddef>

#define LSEQ 256
#define NB   8
#define NC   64
#define TRI  32640    // packed upper triangle (e > i)
#define DPAD 512      // slack for discarded-lane bulk reads

// t = max_c scores, row-packed: g_td[b*TRI + rs(i) + (e-i-1)]
__device__ float g_td[NB * TRI];

__host__ __device__ __forceinline__ int rs_of(int i) {
    return i * 255 - ((i * (i - 1)) >> 1);
}

// ---------------------------------------------------------------------------
// Kernel 1: t[b,i,e] = max over C of scores[b,i,e,:], upper triangle only.
// ---------------------------------------------------------------------------
__global__ void max_kernel(const float* __restrict__ scores) {
    const int i    = blockIdx.x;          // 0 .. 254
    const int b    = blockIdx.y;
    const int warp = threadIdx.x >> 5;
    const int lane = threadIdx.x & 31;
    const int base = b * TRI + rs_of(i) - i - 1;

    for (int e = i + 1 + warp; e < LSEQ; e += 8) {
        const float* p = scores + (((size_t)b * LSEQ + i) * LSEQ + e) * NC;
        float v = fmaxf(p[lane], p[lane + 32]);
        #pragma unroll
        for (int o = 16; o > 0; o >>= 1)
            v = fmaxf(v, __shfl_xor_sync(0xffffffffu, v, o));
        if (lane == 0)
            g_td[base + e] = v;
    }
}

// ---------------------------------------------------------------------------
// Kernel 2: CKY inside (max semiring), one 1024-thread CTA per batch.
// Per pass: FOUR widths (w..w+3). Bulk j in [4, w-1] is legal for all four
// (left diag j <= w-1, right diag w+d-j <= w-1). Right operands adjacent:
// D[ra+d]. Adaptive j-split: M = pow2 >= n cells, G = 1024/M j-groups.
// Combine (tid<256): per width d, reduce G partials + fixups
// (j in {1,2,3} and j in [w, w+d-1], the latter using fresh diagonals),
// partial barrier between widths.
// ---------------------------------------------------------------------------
__global__ __launch_bounds__(1024, 1)
void dp_kernel(const int* __restrict__ lens, float* __restrict__ out) {
    const int b = blockIdx.x;
    extern __shared__ float S[];
    float* D  = S;                          // TRI + DPAD chart
    float* P0 = S + TRI + DPAD;             // 4 x 1024 partials
    float* P1 = P0 + 1024;
    float* P2 = P1 + 1024;
    float* P3 = P2 + 1024;
    int*   rs = (int*)(P3 + 1024);          // rs(i), i in [0,255]
    const float* tb  = g_td + b * TRI;
    const int    tid = threadIdx.x;

    if (tid < 256) rs[tid] = rs_of(tid);
    __syncthreads();
    if (tid < 255) D[rs[tid]] = tb[rs[tid]];        // width-1 diagonal
    for (int q = tid; q < DPAD; q += 1024) D[TRI + q] = -1e30f;

    // Combine-thread state: cached rs values + prefetched t (4 widths).
    int   rsc = 0, rc1 = 0, rc2 = 0, rc3 = 0, lim = 0;
    float t0 = 0.f, t1 = 0.f, t2 = 0.f, t3 = 0.f;
    if (tid < 256) {
        rsc = rs[tid];
        rc1 = rs[tid < 255 ? tid + 1 : 255];
        rc2 = rs[tid < 254 ? tid + 2 : 255];
        rc3 = rs[tid < 253 ? tid + 3 : 255];
        lim = rsc + 254 - tid;              // last valid index of row tid
        int i0 = rsc + 1;
        t0 = tb[i0     < lim ? i0     : lim];
        t1 = tb[i0 + 1 < lim ? i0 + 1 : lim];
        t2 = tb[i0 + 2 < lim ? i0 + 2 : lim];
        t3 = tb[i0 + 3 < lim ? i0 + 3 : lim];
    }
    __syncthreads();

    for (int w = 2; w < LSEQ; w += 4) {
        const int n = LSEQ - w;             // cells at base width w
        int s = 8;
        if (n <= 128) s = 7;
        if (n <= 64)  s = 6;
        const int G  = 1024 >> s;
        const int c  = tid & ((1 << s) - 1);
        const int g  = tid >> s;

        // ---- bulk: j in [4, w-1], all four widths
        if (c < n) {
            float a0 = -1e30f, a1 = -1e30f, a2 = -1e30f, a3 = -1e30f;
            const int m   = w - 4;
            const int jlo = 4 + ((g * m) >> (10 - s));
            const int jhi = 4 + (((g + 1) * m) >> (10 - s));
            if (jlo < jhi) {
                const int rscb = rs[c];
                int la = rscb + jlo - 1;        // left: stride-1 in j
                int ra = rs[c + jlo] + w - jlo - 1;
                int st = 254 - c - jlo;         // ra step (decrements)
                #pragma unroll 4
                for (int j = jlo; j < jhi; ++j) {
                    const float L = D[la];
                    a0 = fmaxf(a0, L + D[ra]);
                    a1 = fmaxf(a1, L + D[ra + 1]);
                    a2 = fmaxf(a2, L + D[ra + 2]);
                    a3 = fmaxf(a3, L + D[ra + 3]);
                    ++la;
                    ra += st; --st;
                }
            }
            P0[tid] = a0; P1[tid] = a1; P2[tid] = a2; P3[tid] = a3;
        }
        __syncthreads();

        // ---- combine: widths w..w+3 sequentially (tid < 256, cell = tid)
        if (tid < 256) {
            #pragma unroll
            for (int d = 0; d < 4; ++d) {
                const int wd = w + d;
                if (wd <= 255) {
                    const int nd = LSEQ - wd;
                    if (tid < nd) {
                        const float* Pd = (d == 0) ? P0 : (d == 1) ? P1
                                        : (d == 2) ? P2 : P3;
                        float v = Pd[tid];
                        for (int k = 1; k < G; ++k)
                            v = fmaxf(v, Pd[(k << s) + tid]);
                        // low fixups: j = 1,2,3 (old diagonals)
                        v = fmaxf(v, D[rsc] + D[rc1 + wd - 2]);
                        if (wd >= 3) v = fmaxf(v, D[rsc + 1] + D[rc2 + wd - 3]);
                        if (wd >= 4) v = fmaxf(v, D[rsc + 2] + D[rc3 + wd - 4]);
                        // high fixups: j in [w, wd-1] (left diag fresh)
                        for (int j = w > 4 ? w : 4; j < wd; ++j)
                            v = fmaxf(v, D[rsc + j - 1] + D[rs[tid + j] + wd - j - 1]);
                        const float tt = (d == 0) ? t0 : (d == 1) ? t1
                                       : (d == 2) ? t2 : t3;
                        D[rsc + wd - 1] = v + tt;
                    }
                    asm volatile("bar.sync 1, 256;" ::: "memory");
                }
            }
            // prefetch t for next pass (widths w+4 .. w+7), clamped
            int i0 = rsc + w + 3;
            t0 = tb[i0     < lim ? i0     : lim];
            t1 = tb[i0 + 1 < lim ? i0 + 1 : lim];
            t2 = tb[i0 + 2 < lim ? i0 + 2 : lim];
            t3 = tb[i0 + 3 < lim ? i0 + 3 : lim];
        }
        __syncthreads();
    }

    if (tid == 0) {
        int len = lens[b];
        len = len < 1 ? 1 : (len > 255 ? 255 : len);
        out[b] = D[len - 1];                // s[0, len] = D[rs(0)+len-1]
    }
}

// ---------------------------------------------------------------------------
extern "C" void kernel_launch(void* const* d_in, const int* in_sizes, int n_in,
                              void* d_out, int out_size) {
    const float* scores = (const float*)d_in[0];
    const int*   lens   = (const int*)d_in[1];
    float*       out    = (float*)d_out;
    (void)in_sizes; (void)n_in; (void)out_size;

    const int smem = (TRI + DPAD + 4 * 1024 + 256) * (int)sizeof(float);
    cudaFuncSetAttribute(dp_kernel,
                         cudaFuncAttributeMaxDynamicSharedMemorySize, smem);

    max_kernel<<<dim3(LSEQ - 1, NB), 256>>>(scores);
    dp_kernel<<<NB, 1024, smem>>>(lens, out);
}

// round 7
// speedup vs baseline: 1.0765x; 1.0765x over previous
#include <cuda_runtime.h>
#include <cstddef>

#define LSEQ 256
#define NB   8
#define NC   64
#define TRI  32640    // packed upper triangle (e > i)
#define DPAD 512      // slack for discarded-lane bulk reads

// t = max_c scores, row-packed: g_td[b*TRI + rs(i) + (e-i-1)]
__device__ float g_td[NB * TRI];

__host__ __device__ __forceinline__ int rs_of(int i) {
    return i * 255 - ((i * (i - 1)) >> 1);
}

// ---------------------------------------------------------------------------
// Kernel 1: t[b,i,e] = max over C of scores[b,i,e,:], upper triangle only.
// ---------------------------------------------------------------------------
__global__ void max_kernel(const float* __restrict__ scores) {
    const int i    = blockIdx.x;          // 0 .. 254
    const int b    = blockIdx.y;
    const int warp = threadIdx.x >> 5;
    const int lane = threadIdx.x & 31;
    const int base = b * TRI + rs_of(i) - i - 1;

    for (int e = i + 1 + warp; e < LSEQ; e += 8) {
        const float* p = scores + (((size_t)b * LSEQ + i) * LSEQ + e) * NC;
        float v = fmaxf(p[lane], p[lane + 32]);
        #pragma unroll
        for (int o = 16; o > 0; o >>= 1)
            v = fmaxf(v, __shfl_xor_sync(0xffffffffu, v, o));
        if (lane == 0)
            g_td[base + e] = v;
    }
}

// ---------------------------------------------------------------------------
// Kernel 2: CKY inside (max semiring), one 1024-thread CTA per batch.
// Per pass: 4 widths (w..w+3).
//  Bulk (1024 thr, adaptive j-split): j in [4, w-1], legal for all 4 widths;
//    right operands adjacent (D[ra+d]). Partials in P[d][tid].
//  Pre-combine (1024 thr): thread (d = tid>>8, cc) reduces the G group
//    partials of width w+d at cell cc into VV[d][cc].
//  Serial tail (tid<256, bar.sync 1,256 between widths): boundary terms
//    j in [1,3] and j in [max(w,4), wd-1] (<=6 per width; fresh diagonals
//    visible after the partial barrier; max idempotent so the overlap in the
//    first pass is harmless), + t, store.
// ---------------------------------------------------------------------------
__global__ __launch_bounds__(1024, 1)
void dp_kernel(const int* __restrict__ lens, float* __restrict__ out) {
    const int b = blockIdx.x;
    extern __shared__ float S[];
    float* D  = S;                          // TRI + DPAD chart
    float* P0 = S + TRI + DPAD;             // 4 x 1024 bulk partials
    float* VV = P0 + 4 * 1024;              // 4 x 256 pre-combined values
    int*   rs = (int*)(VV + 4 * 256);       // rs(i), i in [0,255]
    const float* tb  = g_td + b * TRI;
    const int    tid = threadIdx.x;

    if (tid < 256) rs[tid] = rs_of(tid);
    __syncthreads();
    if (tid < 255) D[rs[tid]] = tb[rs[tid]];        // width-1 diagonal
    for (int q = tid; q < DPAD; q += 1024) D[TRI + q] = -1e30f;

    // Serial-thread state: cached row offsets + prefetched t for widths 2..5.
    int   rsc = 0, rs1 = 0, rs2 = 0, rs3 = 0, lim = 0;
    float t0 = 0.f, t1 = 0.f, t2 = 0.f, t3 = 0.f;
    if (tid < 256) {
        rsc = rs[tid];
        rs1 = rs[tid < 255 ? tid + 1 : 255];
        rs2 = rs[tid < 254 ? tid + 2 : 255];
        rs3 = rs[tid < 253 ? tid + 3 : 255];
        lim = rsc + 254 - tid;               // last valid index of row tid
        if (lim > TRI - 1) lim = TRI - 1;    // row 255 has no cells
        int i0 = rsc + 1;
        t0 = tb[i0     < lim ? i0     : lim];
        t1 = tb[i0 + 1 < lim ? i0 + 1 : lim];
        t2 = tb[i0 + 2 < lim ? i0 + 2 : lim];
        t3 = tb[i0 + 3 < lim ? i0 + 3 : lim];
    }
    __syncthreads();

    for (int w = 2; w < LSEQ; w += 4) {
        const int n = LSEQ - w;              // cells at base width w
        const int s = (n > 128) ? 8 : (n > 64 ? 7 : 6);
        const int c = tid & ((1 << s) - 1);
        const int g = tid >> s;

        // ---- bulk: j in [4, w-1] for all four widths
        float a0 = -1e30f, a1 = -1e30f, a2 = -1e30f, a3 = -1e30f;
        if (c < n && w > 4) {
            const int m   = w - 4;
            const int jlo = 4 + ((g * m) >> (10 - s));
            const int jhi = 4 + (((g + 1) * m) >> (10 - s));
            if (jlo < jhi) {
                int la = rs[c] + jlo - 1;        // left: stride-1 in j
                int ra = rs[c + jlo] + w - jlo - 1;
                int st = 254 - c - jlo;          // ra step (decrements)
                #pragma unroll 4
                for (int j = jlo; j < jhi; ++j) {
                    const float L = D[la];
                    a0 = fmaxf(a0, L + D[ra]);
                    a1 = fmaxf(a1, L + D[ra + 1]);
                    a2 = fmaxf(a2, L + D[ra + 2]);
                    a3 = fmaxf(a3, L + D[ra + 3]);
                    ++la;
                    ra += st; --st;
                }
            }
        }
        P0[tid]        = a0;
        P0[1024 + tid] = a1;
        P0[2048 + tid] = a2;
        P0[3072 + tid] = a3;
        __syncthreads();

        // ---- pre-combine: reduce G group-partials per (width d, cell cc)
        {
            const int d  = tid >> 8;
            const int cc = tid & 255;
            const int G  = 1024 >> s;
            const float* PP = P0 + (d << 10);
            float v = -1e30f;
            if (cc < n) {
                #pragma unroll 4
                for (int k = 0; k < G; ++k)
                    v = fmaxf(v, PP[(k << s) + cc]);
            }
            VV[(d << 8) + cc] = v;
        }
        __syncthreads();

        // ---- serial tail: boundary terms + store, one width at a time
        if (tid < 256) {
            #pragma unroll
            for (int d = 0; d < 4; ++d) {
                const int wd = w + d;
                if (wd <= 255 && tid < LSEQ - wd) {
                    float v = VV[(d << 8) + tid];
                    v = fmaxf(v, D[rsc] + D[rs1 + wd - 2]);            // j=1
                    if (wd >= 3) v = fmaxf(v, D[rsc + 1] + D[rs2 + wd - 3]); // j=2
                    if (wd >= 4) v = fmaxf(v, D[rsc + 2] + D[rs3 + wd - 4]); // j=3
                    for (int j = (w > 4 ? w : 4); j < wd; ++j)          // high
                        v = fmaxf(v, D[rsc + j - 1] + D[rs[tid + j] + wd - j - 1]);
                    const float tt = (d == 0) ? t0 : (d == 1) ? t1
                                   : (d == 2) ? t2 : t3;
                    D[rsc + wd - 1] = v + tt;
                }
                asm volatile("bar.sync 1, 256;" ::: "memory");
            }
            // prefetch t for next pass (widths w+4..w+7), clamped to row end
            int i0 = rsc + w + 3;
            t0 = tb[i0     < lim ? i0     : lim];
            t1 = tb[i0 + 1 < lim ? i0 + 1 : lim];
            t2 = tb[i0 + 2 < lim ? i0 + 2 : lim];
            t3 = tb[i0 + 3 < lim ? i0 + 3 : lim];
        }
        __syncthreads();
    }

    if (tid == 0) {
        int len = lens[b];
        len = len < 1 ? 1 : (len > 255 ? 255 : len);
        out[b] = D[len - 1];                 // s[0, len] = D[rs(0)+len-1]
    }
}

// ---------------------------------------------------------------------------
extern "C" void kernel_launch(void* const* d_in, const int* in_sizes, int n_in,
                              void* d_out, int out_size) {
    const float* scores = (const float*)d_in[0];
    const int*   lens   = (const int*)d_in[1];
    float*       out    = (float*)d_out;
    (void)in_sizes; (void)n_in; (void)out_size;

    const int smem = (TRI + DPAD + 4 * 1024 + 4 * 256 + 256) * (int)sizeof(float);
    cudaFuncSetAttribute(dp_kernel,
                         cudaFuncAttributeMaxDynamicSharedMemorySize, smem);

    max_kernel<<<dim3(LSEQ - 1, NB), 256>>>(scores);
    dp_kernel<<<NB, 1024, smem>>>(lens, out);
}